// round 15
// baseline (speedup 1.0000x reference)
#include <cuda_runtime.h>
#include <cuda_fp16.h>
#include <cstdint>
#include <math.h>

#define BB   16
#define CC   512
#define HWW  1024
#define ABUF ((size_t)BB*CC*HWW)      // 8M elements

// Scratch (__device__ globals; no allocs allowed)
__device__ __half g_hxT[ABUF];   // normalized x, [b][hw][c] fp16; reused as O
__device__ __half g_hyT[ABUF];   // normalized y, [b][hw][c] fp16
__device__ __half g_qT [ABUF];   // [b][hw][c]
__device__ __half g_kT [ABUF];   // [b][hw][c]
__device__ __half g_v2 [ABUF];   // [b][c][hw]
__device__ __half g_wh [4*(size_t)CC*CC];       // fp16 weights: q,k,v,p
__device__ __half g_sh [(size_t)BB*HWW*HWW];    // fp16 scores -> probs (in-place)

__device__ __forceinline__ uint32_t smem_u32(const void* p) {
    uint32_t a;
    asm("{ .reg .u64 t; cvta.to.shared.u64 t, %1; cvt.u32.u64 %0, t; }" : "=r"(a) : "l"(p));
    return a;
}
#define CP_ASYNC16(sa, ga) \
    asm volatile("cp.async.cg.shared.global [%0], [%1], 16;" :: "r"(sa), "l"(ga) : "memory")
#define CP_COMMIT() asm volatile("cp.async.commit_group;" ::: "memory")
#define CP_WAIT1()  asm volatile("cp.async.wait_group 1;" ::: "memory")
#define CP_WAIT0()  asm volatile("cp.async.wait_group 0;" ::: "memory")

__device__ __forceinline__ void ldsm4(uint32_t& r0, uint32_t& r1, uint32_t& r2,
                                      uint32_t& r3, uint32_t addr) {
    asm volatile("ldmatrix.sync.aligned.m8n8.x4.shared.b16 {%0,%1,%2,%3}, [%4];"
                 : "=r"(r0), "=r"(r1), "=r"(r2), "=r"(r3) : "r"(addr));
}
#define HMMA16816(acc, a, b) \
    asm volatile( \
        "mma.sync.aligned.m16n8k16.row.col.f32.f16.f16.f32 " \
        "{%0,%1,%2,%3},{%4,%5,%6,%7},{%8,%9},{%0,%1,%2,%3};" \
        : "+f"(acc[0]), "+f"(acc[1]), "+f"(acc[2]), "+f"(acc[3]) \
        : "r"(a[0]), "r"(a[1]), "r"(a[2]), "r"(a[3]), "r"(b[0]), "r"(b[1]))

// 128x128 tile, 3-stage cp.async, K-chunk 64 halves, XOR swizzle, ldmatrix.x4,
// register-double-buffered k16 steps. Declared inside the per-tile loop.
#define GEMM_MAINLOOP(Ab, Bb, lda, ldb, NC)                                          \
    uint32_t smb = smem_u32(sm);                                                      \
    auto load = [&](int c, int s) {                                                   \
        int k0 = c * 64;                                                              \
        _Pragma("unroll")                                                             \
        for (int j = 0; j < 8; j++) {                                                 \
            int idx2 = t + 128 * j;                                                   \
            int r = idx2 >> 3, cq = idx2 & 7;                                         \
            int cs = cq ^ (r & 7);                                                    \
            const __half* ga = Ab + (size_t)(m0 + r) * lda + k0 + cq * 8;             \
            const __half* gb = Bb + (size_t)(n0 + r) * ldb + k0 + cq * 8;             \
            uint32_t so = (uint32_t)(s * STGB + r * 128 + cs * 16);                   \
            CP_ASYNC16(smb + so, ga);                                                 \
            CP_ASYNC16(smb + (uint32_t)TILEB + so, gb);                               \
        }                                                                             \
    };                                                                                \
    auto ldfrag = [&](uint32_t aBase, uint32_t bBase, int s16,                        \
                      uint32_t (&af)[4][4], uint32_t (&bf)[8][2]) {                   \
        uint32_t slA = (uint32_t)(((2 * s16 + hiA) ^ lo7) << 4);                      \
        uint32_t slB = (uint32_t)(((2 * s16 + hiB) ^ lo7) << 4);                      \
        uint32_t aAddr = aBase + rowA_off + slA;                                      \
        uint32_t bAddr = bBase + rowB_off + slB;                                      \
        _Pragma("unroll")                                                             \
        for (int i = 0; i < 4; i++)                                                   \
            ldsm4(af[i][0], af[i][1], af[i][2], af[i][3],                             \
                  aAddr + (uint32_t)(i * 16 * 128));                                  \
        _Pragma("unroll")                                                             \
        for (int p = 0; p < 4; p++)                                                   \
            ldsm4(bf[2 * p][0], bf[2 * p][1], bf[2 * p + 1][0], bf[2 * p + 1][1],     \
                  bAddr + (uint32_t)(p * 16 * 128));                                  \
    };                                                                                \
    load(0, 0); CP_COMMIT();                                                          \
    if (NC > 1) { load(1, 1); CP_COMMIT(); }                                          \
    uint32_t af[2][4][4], bf[2][8][2];                                                \
    for (int c = 0; c < NC; c++) {                                                    \
        if (c + 1 < NC) CP_WAIT1(); else CP_WAIT0();                                  \
        __syncthreads();                                                              \
        uint32_t aBase = smb + (uint32_t)((c % 3) * STGB);                            \
        uint32_t bBase = aBase + (uint32_t)TILEB;                                     \
        ldfrag(aBase, bBase, 0, af[0], bf[0]);                                        \
        if (c + 2 < NC) { load(c + 2, (c + 2) % 3); CP_COMMIT(); }                    \
        _Pragma("unroll")                                                             \
        for (int s16 = 0; s16 < 4; s16++) {                                           \
            if (s16 < 3) ldfrag(aBase, bBase, s16 + 1, af[(s16 + 1) & 1], bf[(s16 + 1) & 1]); \
            uint32_t (&a)[4][4] = af[s16 & 1];                                        \
            uint32_t (&b)[8][2] = bf[s16 & 1];                                        \
            _Pragma("unroll")                                                         \
            for (int i = 0; i < 4; i++)                                               \
                _Pragma("unroll")                                                     \
                for (int j = 0; j < 8; j++)                                           \
                    HMMA16816(acc[i][j], a[i], b[j]);                                 \
        }                                                                             \
    }

// ---------------------------------------------------------------------------
// Persistent merged q/k/v kernel. Tile idx: bx = idx&3 (c-tile), by = (idx>>2)&7
// (hw-tile), z = idx>>5: bz = z&15, which = z>>4 (0=q,1=k,2=v). T = 1536.
// ---------------------------------------------------------------------------
__global__ __launch_bounds__(128, 2)
void mma_qkv(const __half* __restrict__ hyT, const __half* __restrict__ hxT,
             const __half* __restrict__ wh,
             __half* __restrict__ qT, __half* __restrict__ kT, __half* __restrict__ v2,
             const float* __restrict__ bq, const float* __restrict__ bk,
             const float* __restrict__ bv, int T)
{
    extern __shared__ float sm[];
    const int TILEB = 128 * 128, STGB = 2 * TILEB;
    const long AS = (long)CC * HWW;

    int t = threadIdx.x, lane = t & 31, w = t >> 5;
    int wr = w & 1, wc = w >> 1;
    int g = lane >> 2, tg = lane & 3;
    int lo7 = lane & 7;
    int hiA = lane >> 4, hiB = (lane >> 3) & 1;
    uint32_t rowA_off = (uint32_t)((wr * 64 + (lane & 15)) * 128);
    uint32_t rowB_off = (uint32_t)((wc * 64 + lo7 + ((lane & 16) >> 1)) * 128);

    for (int idx = blockIdx.x; idx < T; idx += gridDim.x) {
        int bx = idx & 3, by = (idx >> 2) & 7, z = idx >> 5;
        int bz = z & 15, which = z >> 4;
        int m0 = by * 128, n0 = bx * 128;

        const __half* Ab = (which == 0 ? hyT : hxT) + (size_t)bz * AS;
        const __half* Bb = wh + (size_t)which * CC * CC;
        const float* bias = which == 0 ? bq : (which == 1 ? bk : bv);

        float acc[4][8][4];
        #pragma unroll
        for (int i = 0; i < 4; i++)
            #pragma unroll
            for (int j = 0; j < 8; j++)
                #pragma unroll
                for (int q = 0; q < 4; q++) acc[i][j][q] = 0.f;

        GEMM_MAINLOOP(Ab, Bb, CC, CC, 8)

        if (which < 2) {
            __half* Cb = (which ? kT : qT) + (size_t)bz * AS;
            int mrow = m0 + wr * 64, ncol = n0 + wc * 64;
            #pragma unroll
            for (int i = 0; i < 4; i++) {
                int r0 = mrow + i * 16 + g, r1 = r0 + 8;
                #pragma unroll
                for (int j = 0; j < 8; j++) {
                    int cc = ncol + j * 8 + 2 * tg;
                    float b0 = __ldg(&bias[cc]), b1 = __ldg(&bias[cc + 1]);
                    *(__half2*)(Cb + (size_t)r0 * CC + cc) =
                        __floats2half2_rn(acc[i][j][0] + b0, acc[i][j][1] + b1);
                    *(__half2*)(Cb + (size_t)r1 * CC + cc) =
                        __floats2half2_rn(acc[i][j][2] + b0, acc[i][j][3] + b1);
                }
            }
        } else {
            // transposed store via fp32 smem staging (pad 129)
            __half* Cb = v2 + (size_t)bz * AS;
            __syncthreads();
            #pragma unroll
            for (int i = 0; i < 4; i++) {
                int rl0 = wr * 64 + i * 16 + g, rl1 = rl0 + 8;
                #pragma unroll
                for (int j = 0; j < 8; j++) {
                    int nl = wc * 64 + j * 8 + 2 * tg;
                    float b0 = __ldg(&bias[n0 + nl]), b1 = __ldg(&bias[n0 + nl + 1]);
                    sm[(nl + 0) * 129 + rl0] = acc[i][j][0] + b0;
                    sm[(nl + 1) * 129 + rl0] = acc[i][j][1] + b1;
                    sm[(nl + 0) * 129 + rl1] = acc[i][j][2] + b0;
                    sm[(nl + 1) * 129 + rl1] = acc[i][j][3] + b1;
                }
            }
            __syncthreads();
            #pragma unroll 4
            for (int rr = 0; rr < 32; rr++) {
                int rloc = w * 32 + rr;
                __half* dst = Cb + (size_t)(n0 + rloc) * HWW + m0;
                const float* srcr = sm + rloc * 129;
                #pragma unroll
                for (int k2 = 0; k2 < 4; k2++)
                    dst[lane + 32 * k2] = __float2half_rn(srcr[lane + 32 * k2]);
            }
        }
        __syncthreads();   // protect smem before next tile's loads
    }
}

// ---------------------------------------------------------------------------
// Persistent generic fp16 GEMM. Tile idx -> bx = idx%gx, by = (idx/gx)%gy,
// bz = idx/(gx*gy). EPI: 1=*scale->half | 2=none->half | 3=+bias[m]+resid->f32
// ---------------------------------------------------------------------------
template<int EPI>
__global__ __launch_bounds__(128, 2)
void mma_gemm(const __half* __restrict__ A, const __half* __restrict__ B,
              void* __restrict__ Cv, const float* __restrict__ bias,
              const float* __restrict__ resid,
              int NC, int lda, int ldb, int ldc,
              long aB, long bB, long cB, float scale,
              int gx, int gy, int T)
{
    extern __shared__ float sm[];
    const int TILEB = 128 * 128, STGB = 2 * TILEB;

    int t = threadIdx.x, lane = t & 31, w = t >> 5;
    int wr = w & 1, wc = w >> 1;
    int g = lane >> 2, tg = lane & 3;
    int lo7 = lane & 7;
    int hiA = lane >> 4, hiB = (lane >> 3) & 1;
    uint32_t rowA_off = (uint32_t)((wr * 64 + (lane & 15)) * 128);
    uint32_t rowB_off = (uint32_t)((wc * 64 + lo7 + ((lane & 16) >> 1)) * 128);

    for (int idx = blockIdx.x; idx < T; idx += gridDim.x) {
        int bx = idx % gx;
        int rem = idx / gx;
        int by = rem % gy;
        int bz = rem / gy;
        int m0 = by * 128, n0 = bx * 128;
        const __half* Ab = A + (size_t)bz * aB;
        const __half* Bb = B + (size_t)bz * bB;

        float acc[4][8][4];
        #pragma unroll
        for (int i = 0; i < 4; i++)
            #pragma unroll
            for (int j = 0; j < 8; j++)
                #pragma unroll
                for (int q = 0; q < 4; q++) acc[i][j][q] = 0.f;

        GEMM_MAINLOOP(Ab, Bb, lda, ldb, NC)

        int mrow = m0 + wr * 64, ncol = n0 + wc * 64;
        #pragma unroll
        for (int i = 0; i < 4; i++) {
            int r0 = mrow + i * 16 + g, r1 = r0 + 8;
            float bm0 = 0.f, bm1 = 0.f;
            if (EPI == 3) { bm0 = __ldg(&bias[r0]); bm1 = __ldg(&bias[r1]); }
            #pragma unroll
            for (int j = 0; j < 8; j++) {
                int cc = ncol + j * 8 + 2 * tg;
                float2 v0 = make_float2(acc[i][j][0], acc[i][j][1]);
                float2 v1 = make_float2(acc[i][j][2], acc[i][j][3]);
                if (EPI == 1) {
                    __half* Cb = (__half*)Cv + (size_t)bz * cB;
                    *(__half2*)(Cb + (size_t)r0 * ldc + cc) = __floats2half2_rn(v0.x * scale, v0.y * scale);
                    *(__half2*)(Cb + (size_t)r1 * ldc + cc) = __floats2half2_rn(v1.x * scale, v1.y * scale);
                } else if (EPI == 2) {
                    __half* Cb = (__half*)Cv + (size_t)bz * cB;
                    *(__half2*)(Cb + (size_t)r0 * ldc + cc) = __floats2half2_rn(v0.x, v0.y);
                    *(__half2*)(Cb + (size_t)r1 * ldc + cc) = __floats2half2_rn(v1.x, v1.y);
                } else {
                    float* Cb = (float*)Cv + (size_t)bz * cB;
                    const float* Rb = resid + (size_t)bz * cB;
                    float2 x0 = *(const float2*)(Rb + (size_t)r0 * ldc + cc);
                    float2 x1 = *(const float2*)(Rb + (size_t)r1 * ldc + cc);
                    v0.x += bm0 + x0.x; v0.y += bm0 + x0.y;
                    v1.x += bm1 + x1.x; v1.y += bm1 + x1.y;
                    *(float2*)(Cb + (size_t)r0 * ldc + cc) = v0;
                    *(float2*)(Cb + (size_t)r1 * ldc + cc) = v1;
                }
            }
        }
        __syncthreads();   // protect smem before next tile's loads
    }
}

// ---------------------------------------------------------------------------
// fp32 -> fp16 weight conversion, all 4 matrices in ONE launch (grid.y = mat)
// ---------------------------------------------------------------------------
__global__ void cvt_half4_kernel(const float* __restrict__ s0, const float* __restrict__ s1,
                                 const float* __restrict__ s2, const float* __restrict__ s3,
                                 __half* __restrict__ dst)
{
    const float* srcs[4] = {s0, s1, s2, s3};
    const float* src = srcs[blockIdx.y];
    int i = (blockIdx.x * blockDim.x + threadIdx.x) * 4;
    float4 v = *(const float4*)(src + i);
    __half2* d = (__half2*)(dst + (size_t)blockIdx.y * CC * CC + i);
    d[0] = __floats2half2_rn(v.x, v.y);
    d[1] = __floats2half2_rn(v.z, v.w);
}

// ---------------------------------------------------------------------------
// GroupNorm, both tensors in one launch (grid.y selects x/y), fp16 transposed
// output [b][hw][c]. One block per (b, group).
// ---------------------------------------------------------------------------
__global__ void gn_t_kernel(const float* __restrict__ x0, const float* __restrict__ sc0,
                            const float* __restrict__ bi0, __half* __restrict__ o0,
                            const float* __restrict__ x1, const float* __restrict__ sc1,
                            const float* __restrict__ bi1, __half* __restrict__ o1)
{
    extern __shared__ float xs[];      // 16 * 1026
    __shared__ float shs[8], shq[8], shm2[2];
    const float* x  = blockIdx.y ? x1  : x0;
    const float* sc = blockIdx.y ? sc1 : sc0;
    const float* bi = blockIdx.y ? bi1 : bi0;
    __half* outT    = blockIdx.y ? o1  : o0;
    int bg = blockIdx.x;
    int b = bg >> 5, g = bg & 31;
    const float* xp = x + ((size_t)b * CC + (size_t)g * 16) * HWW;
    int t = threadIdx.x;

    float s = 0.f, sq = 0.f;
    #pragma unroll 4
    for (int j = 0; j < 64; j++) {
        int idx = t + 256 * j;               // idx = c*1024 + hw
        float v = xp[idx];
        xs[(idx >> 10) * 1026 + (idx & 1023)] = v;
        s += v; sq += v * v;
    }
    #pragma unroll
    for (int o = 16; o > 0; o >>= 1) {
        s  += __shfl_xor_sync(0xffffffffu, s,  o);
        sq += __shfl_xor_sync(0xffffffffu, sq, o);
    }
    if ((t & 31) == 0) { shs[t >> 5] = s; shq[t >> 5] = sq; }
    __syncthreads();
    if (t == 0) {
        float S = 0.f, Q = 0.f;
        #pragma unroll
        for (int i = 0; i < 8; i++) { S += shs[i]; Q += shq[i]; }
        float mean = S * (1.f / 16384.f);
        float var  = Q * (1.f / 16384.f) - mean * mean;
        shm2[0] = mean;
        shm2[1] = rsqrtf(var + 1e-6f);
    }
    __syncthreads();
    float mean = shm2[0], rs = shm2[1];
    int cl = t & 15;
    float scv = __ldg(&sc[g * 16 + cl]) * rs;
    float biv = __ldg(&bi[g * 16 + cl]);
    __half* op = outT + (size_t)b * HWW * CC + g * 16;
    #pragma unroll 4
    for (int j = 0; j < 64; j++) {
        int idx = t + 256 * j;
        int hw = idx >> 4;
        op[(size_t)hw * CC + cl] = __float2half_rn((xs[cl * 1026 + hw] - mean) * scv + biv);
    }
}

// ---------------------------------------------------------------------------
// In-place fp16 row softmax: 2 rows per 256-thread block, uint4 loads.
// ---------------------------------------------------------------------------
__global__ void softmax_kernel(__half* __restrict__ Sh)
{
    __shared__ float red[2][4];
    int t = threadIdx.x;
    int r = t >> 7, tt = t & 127;
    int w4 = (t >> 5) & 3;
    size_t row = (size_t)blockIdx.x * 2 + r;
    uint4* p = (uint4*)(Sh + row * HWW);

    uint4 u = p[tt];
    __half2 h[4];
    h[0] = *(__half2*)&u.x; h[1] = *(__half2*)&u.y;
    h[2] = *(__half2*)&u.z; h[3] = *(__half2*)&u.w;
    float2 a[4];
    #pragma unroll
    for (int i = 0; i < 4; i++) a[i] = __half22float2(h[i]);

    float m = a[0].x;
    #pragma unroll
    for (int i = 0; i < 4; i++) m = fmaxf(m, fmaxf(a[i].x, a[i].y));
    #pragma unroll
    for (int o = 16; o > 0; o >>= 1) m = fmaxf(m, __shfl_xor_sync(0xffffffffu, m, o));
    if ((t & 31) == 0) red[r][w4] = m;
    __syncthreads();
    float M = fmaxf(fmaxf(red[r][0], red[r][1]), fmaxf(red[r][2], red[r][3]));
    __syncthreads();

    float s = 0.f;
    #pragma unroll
    for (int i = 0; i < 4; i++) {
        a[i].x = __expf(a[i].x - M); a[i].y = __expf(a[i].y - M);
        s += a[i].x + a[i].y;
    }
    #pragma unroll
    for (int o = 16; o > 0; o >>= 1) s += __shfl_xor_sync(0xffffffffu, s, o);
    if ((t & 31) == 0) red[r][w4] = s;
    __syncthreads();
    float T = red[r][0] + red[r][1] + red[r][2] + red[r][3];
    float inv = 1.0f / T;

    __half2 o2[4];
    #pragma unroll
    for (int i = 0; i < 4; i++) o2[i] = __floats2half2_rn(a[i].x * inv, a[i].y * inv);
    uint4 ou;
    ou.x = *(uint32_t*)&o2[0]; ou.y = *(uint32_t*)&o2[1];
    ou.z = *(uint32_t*)&o2[2]; ou.w = *(uint32_t*)&o2[3];
    p[tt] = ou;
}

// ---------------------------------------------------------------------------
extern "C" void kernel_launch(void* const* d_in, const int* in_sizes, int n_in,
                              void* d_out, int out_size)
{
    const float* x   = (const float*)d_in[0];
    const float* y   = (const float*)d_in[1];
    const float* ns  = (const float*)d_in[2];
    const float* nb  = (const float*)d_in[3];
    const float* n1s = (const float*)d_in[4];
    const float* n1b = (const float*)d_in[5];
    const float* wq  = (const float*)d_in[6];
    const float* bq  = (const float*)d_in[7];
    const float* wk  = (const float*)d_in[8];
    const float* bk  = (const float*)d_in[9];
    const float* wv  = (const float*)d_in[10];
    const float* bv  = (const float*)d_in[11];
    const float* wp  = (const float*)d_in[12];
    const float* bp  = (const float*)d_in[13];
    float* out = (float*)d_out;

    __half *hxT, *hyT, *qT, *kT, *v2, *wh, *sh;
    cudaGetSymbolAddress((void**)&hxT, g_hxT);
    cudaGetSymbolAddress((void**)&hyT, g_hyT);
    cudaGetSymbolAddress((void**)&qT,  g_qT);
    cudaGetSymbolAddress((void**)&kT,  g_kT);
    cudaGetSymbolAddress((void**)&v2,  g_v2);
    cudaGetSymbolAddress((void**)&wh,  g_wh);
    cudaGetSymbolAddress((void**)&sh,  g_sh);
    __half* O = hxT;   // hxT dead after qkv kernel
    __half* whp = wh + 3 * (size_t)CC * CC;

    int nsm = 148;
    cudaDeviceGetAttribute(&nsm, cudaDevAttrMultiProcessorCount, 0);
    int P = 2 * nsm;   // persistent grid: 2 CTAs per SM

    const int SMEM_GEMM = 3 * 2 * 128 * 128;         // 98304 B
    const int SMEM_GN   = 16 * 1026 * sizeof(float); // 65664 B
    cudaFuncSetAttribute(mma_qkv,     cudaFuncAttributeMaxDynamicSharedMemorySize, SMEM_GEMM);
    cudaFuncSetAttribute(mma_gemm<1>, cudaFuncAttributeMaxDynamicSharedMemorySize, SMEM_GEMM);
    cudaFuncSetAttribute(mma_gemm<2>, cudaFuncAttributeMaxDynamicSharedMemorySize, SMEM_GEMM);
    cudaFuncSetAttribute(mma_gemm<3>, cudaFuncAttributeMaxDynamicSharedMemorySize, SMEM_GEMM);
    cudaFuncSetAttribute(gn_t_kernel, cudaFuncAttributeMaxDynamicSharedMemorySize, SMEM_GN);

    const long AS = (long)CC * HWW;
    const long SS = (long)HWW * HWW;
    const float qkscale = 0.044194173824159216f;   // 512^-0.5

    // Weight conversion (1 MB total), single launch
    cvt_half4_kernel<<<dim3(256, 4), 256>>>(wq, wk, wv, wp, wh);

    // GroupNorm x and y, single launch (grid.y selects tensor)
    gn_t_kernel<<<dim3(BB * 32, 2), 256, SMEM_GN>>>(x, ns, nb, hxT, y, n1s, n1b, hyT);

    // q, k, v: persistent, T = 1536 tiles
    {
        int T = 4 * 8 * 3 * BB;
        mma_qkv<<<(P < T ? P : T), 128, SMEM_GEMM>>>(hyT, hxT, wh, qT, kT, v2, bq, bk, bv, T);
    }

    // scores: Sh[i,j] = half(scale * q.kT); T = 8*8*16 = 1024 tiles
    {
        int T = 8 * 8 * BB;
        mma_gemm<1><<<(P < T ? P : T), 128, SMEM_GEMM>>>(qT, kT, sh, nullptr, nullptr,
                                                          8, CC, CC, HWW, AS, AS, SS, qkscale, 8, 8, T);
    }

    softmax_kernel<<<BB * HWW / 2, 256>>>(sh);

    // O[i, c] = sum_j probs[i,j] * v2[c,j]; T = 4*8*16 = 512 tiles
    {
        int T = 4 * 8 * BB;
        mma_gemm<2><<<(P < T ? P : T), 128, SMEM_GEMM>>>(sh, v2, O, nullptr, nullptr,
                                                          16, HWW, HWW, CC, SS, AS, AS, 0.f, 4, 8, T);
    }

    // out[oc, hw] = wp.O + bp + x; T = 8*4*16 = 512 tiles
    {
        int T = 8 * 4 * BB;
        mma_gemm<3><<<(P < T ? P : T), 128, SMEM_GEMM>>>(whp, O, out, bp, x,
                                                          8, CC, CC, HWW, 0, AS, AS, 0.f, 8, 4, T);
    }
}

// round 16
// speedup vs baseline: 1.1225x; 1.1225x over previous
#include <cuda_runtime.h>
#include <cuda_fp16.h>
#include <cstdint>
#include <math.h>

#define BB   16
#define CC   512
#define HWW  1024
#define ABUF ((size_t)BB*CC*HWW)      // 8M elements

// Scratch (__device__ globals; no allocs allowed)
__device__ __half g_hxT[ABUF];   // normalized x, [b][hw][c] fp16; reused as O
__device__ __half g_hyT[ABUF];   // normalized y, [b][hw][c] fp16
__device__ __half g_qT [ABUF];   // [b][hw][c]
__device__ __half g_kT [ABUF];   // [b][hw][c]
__device__ __half g_v2 [ABUF];   // [b][c][hw]
__device__ __half g_wh [4*(size_t)CC*CC];       // fp16 weights: q,k,v,p
__device__ __half g_sh [(size_t)BB*HWW*HWW];    // fp16 scores -> probs (in-place)

__device__ __forceinline__ uint32_t smem_u32(const void* p) {
    uint32_t a;
    asm("{ .reg .u64 t; cvta.to.shared.u64 t, %1; cvt.u32.u64 %0, t; }" : "=r"(a) : "l"(p));
    return a;
}
#define CP_ASYNC16(sa, ga) \
    asm volatile("cp.async.cg.shared.global [%0], [%1], 16;" :: "r"(sa), "l"(ga) : "memory")
#define CP_COMMIT() asm volatile("cp.async.commit_group;" ::: "memory")
#define CP_WAIT1()  asm volatile("cp.async.wait_group 1;" ::: "memory")
#define CP_WAIT0()  asm volatile("cp.async.wait_group 0;" ::: "memory")

__device__ __forceinline__ void ldsm4(uint32_t& r0, uint32_t& r1, uint32_t& r2,
                                      uint32_t& r3, uint32_t addr) {
    asm volatile("ldmatrix.sync.aligned.m8n8.x4.shared.b16 {%0,%1,%2,%3}, [%4];"
                 : "=r"(r0), "=r"(r1), "=r"(r2), "=r"(r3) : "r"(addr));
}
#define HMMA16816(acc, a, b) \
    asm volatile( \
        "mma.sync.aligned.m16n8k16.row.col.f32.f16.f16.f32 " \
        "{%0,%1,%2,%3},{%4,%5,%6,%7},{%8,%9},{%0,%1,%2,%3};" \
        : "+f"(acc[0]), "+f"(acc[1]), "+f"(acc[2]), "+f"(acc[3]) \
        : "r"(a[0]), "r"(a[1]), "r"(a[2]), "r"(a[3]), "r"(b[0]), "r"(b[1]))

// 128x128 tile, 3-stage cp.async, K-chunk 64 halves, XOR swizzle, ldmatrix.x4,
// register-double-buffered k16 steps. NC must be a compile-time constant at
// the expansion site for full unroll.
#define GEMM_MAINLOOP(Ab, Bb, lda, ldb, NC)                                          \
    uint32_t smb = smem_u32(sm);                                                      \
    uint32_t rowA_off = (uint32_t)((wr * 64 + (lane & 15)) * 128);                    \
    uint32_t rowB_off = (uint32_t)((wc * 64 + lo7 + ((lane & 16) >> 1)) * 128);       \
    auto load = [&](int c, int s) {                                                   \
        int k0 = c * 64;                                                              \
        _Pragma("unroll")                                                             \
        for (int j = 0; j < 8; j++) {                                                 \
            int idx2 = t + 128 * j;                                                   \
            int r = idx2 >> 3, cq = idx2 & 7;                                         \
            int cs = cq ^ (r & 7);                                                    \
            const __half* ga = Ab + (size_t)(m0 + r) * lda + k0 + cq * 8;             \
            const __half* gb = Bb + (size_t)(n0 + r) * ldb + k0 + cq * 8;             \
            uint32_t so = (uint32_t)(s * STGB + r * 128 + cs * 16);                   \
            CP_ASYNC16(smb + so, ga);                                                 \
            CP_ASYNC16(smb + (uint32_t)TILEB + so, gb);                               \
        }                                                                             \
    };                                                                                \
    auto ldfrag = [&](uint32_t aBase, uint32_t bBase, int s16,                        \
                      uint32_t (&af)[4][4], uint32_t (&bf)[8][2]) {                   \
        uint32_t slA = (uint32_t)(((2 * s16 + hiA) ^ lo7) << 4);                      \
        uint32_t slB = (uint32_t)(((2 * s16 + hiB) ^ lo7) << 4);                      \
        uint32_t aAddr = aBase + rowA_off + slA;                                      \
        uint32_t bAddr = bBase + rowB_off + slB;                                      \
        _Pragma("unroll")                                                             \
        for (int i = 0; i < 4; i++)                                                   \
            ldsm4(af[i][0], af[i][1], af[i][2], af[i][3],                             \
                  aAddr + (uint32_t)(i * 16 * 128));                                  \
        _Pragma("unroll")                                                             \
        for (int p = 0; p < 4; p++)                                                   \
            ldsm4(bf[2 * p][0], bf[2 * p][1], bf[2 * p + 1][0], bf[2 * p + 1][1],     \
                  bAddr + (uint32_t)(p * 16 * 128));                                  \
    };                                                                                \
    load(0, 0); CP_COMMIT();                                                          \
    if (NC > 1) { load(1, 1); CP_COMMIT(); }                                          \
    uint32_t af[2][4][4], bf[2][8][2];                                                \
    _Pragma("unroll")                                                                 \
    for (int c = 0; c < NC; c++) {                                                    \
        if (c + 1 < NC) CP_WAIT1(); else CP_WAIT0();                                  \
        __syncthreads();                                                              \
        uint32_t aBase = smb + (uint32_t)((c % 3) * STGB);                            \
        uint32_t bBase = aBase + (uint32_t)TILEB;                                     \
        ldfrag(aBase, bBase, 0, af[0], bf[0]);                                        \
        if (c + 2 < NC) { load(c + 2, (c + 2) % 3); CP_COMMIT(); }                    \
        _Pragma("unroll")                                                             \
        for (int s16 = 0; s16 < 4; s16++) {                                           \
            if (s16 < 3) ldfrag(aBase, bBase, s16 + 1, af[(s16 + 1) & 1], bf[(s16 + 1) & 1]); \
            uint32_t (&a)[4][4] = af[s16 & 1];                                        \
            uint32_t (&b)[8][2] = bf[s16 & 1];                                        \
            _Pragma("unroll")                                                         \
            for (int i = 0; i < 4; i++)                                               \
                _Pragma("unroll")                                                     \
                for (int j = 0; j < 8; j++)                                           \
                    HMMA16816(acc[i][j], a[i], b[j]);                                 \
        }                                                                             \
    }

// ---------------------------------------------------------------------------
// Merged q/k/v kernel: grid (4, 8, 48); z = batch + 16*which (0=q,1=k,2=v).
// q/k: +bias[n] half store [hw][c]. v: +bias[n] transposed half store [c][hw].
// ---------------------------------------------------------------------------
__global__ __launch_bounds__(128, 2)
void mma_qkv(const __half* __restrict__ hyT, const __half* __restrict__ hxT,
             const __half* __restrict__ wh,
             __half* __restrict__ qT, __half* __restrict__ kT, __half* __restrict__ v2,
             const float* __restrict__ bq, const float* __restrict__ bk,
             const float* __restrict__ bv)
{
    extern __shared__ float sm[];
    const int TILEB = 128 * 128, STGB = 2 * TILEB;
    const long AS = (long)CC * HWW;

    int t = threadIdx.x, lane = t & 31, w = t >> 5;
    int wr = w & 1, wc = w >> 1;
    int g = lane >> 2, tg = lane & 3;
    int lo7 = lane & 7;
    int hiA = lane >> 4, hiB = (lane >> 3) & 1;
    int z = blockIdx.z;
    int bz = z & 15, which = z >> 4;
    int m0 = blockIdx.y * 128, n0 = blockIdx.x * 128;

    const __half* Ab = (which == 0 ? hyT : hxT) + (size_t)bz * AS;
    const __half* Bb = wh + (size_t)which * CC * CC;
    const float* bias = which == 0 ? bq : (which == 1 ? bk : bv);

    float acc[4][8][4];
    #pragma unroll
    for (int i = 0; i < 4; i++)
        #pragma unroll
        for (int j = 0; j < 8; j++)
            #pragma unroll
            for (int q = 0; q < 4; q++) acc[i][j][q] = 0.f;

    GEMM_MAINLOOP(Ab, Bb, CC, CC, 8)

    if (which < 2) {
        __half* Cb = (which ? kT : qT) + (size_t)bz * AS;
        int mrow = m0 + wr * 64, ncol = n0 + wc * 64;
        #pragma unroll
        for (int i = 0; i < 4; i++) {
            int r0 = mrow + i * 16 + g, r1 = r0 + 8;
            #pragma unroll
            for (int j = 0; j < 8; j++) {
                int cc = ncol + j * 8 + 2 * tg;
                float b0 = __ldg(&bias[cc]), b1 = __ldg(&bias[cc + 1]);
                *(__half2*)(Cb + (size_t)r0 * CC + cc) =
                    __floats2half2_rn(acc[i][j][0] + b0, acc[i][j][1] + b1);
                *(__half2*)(Cb + (size_t)r1 * CC + cc) =
                    __floats2half2_rn(acc[i][j][2] + b0, acc[i][j][3] + b1);
            }
        }
    } else {
        // transposed store via fp32 smem staging (pad 129)
        __half* Cb = v2 + (size_t)bz * AS;
        __syncthreads();
        #pragma unroll
        for (int i = 0; i < 4; i++) {
            int rl0 = wr * 64 + i * 16 + g, rl1 = rl0 + 8;
            #pragma unroll
            for (int j = 0; j < 8; j++) {
                int nl = wc * 64 + j * 8 + 2 * tg;
                float b0 = __ldg(&bias[n0 + nl]), b1 = __ldg(&bias[n0 + nl + 1]);
                sm[(nl + 0) * 129 + rl0] = acc[i][j][0] + b0;
                sm[(nl + 1) * 129 + rl0] = acc[i][j][1] + b1;
                sm[(nl + 0) * 129 + rl1] = acc[i][j][2] + b0;
                sm[(nl + 1) * 129 + rl1] = acc[i][j][3] + b1;
            }
        }
        __syncthreads();
        #pragma unroll 4
        for (int rr = 0; rr < 32; rr++) {
            int rloc = w * 32 + rr;
            __half* dst = Cb + (size_t)(n0 + rloc) * HWW + m0;
            const float* srcr = sm + rloc * 129;
            #pragma unroll
            for (int k2 = 0; k2 < 4; k2++)
                dst[lane + 32 * k2] = __float2half_rn(srcr[lane + 32 * k2]);
        }
    }
}

// ---------------------------------------------------------------------------
// Generic fp16 GEMM, NC compile-time.
// EPI: 1=*scale->half | 2=none->half | 3=+bias[m]+resid->f32
// ---------------------------------------------------------------------------
template<int EPI, int NC>
__global__ __launch_bounds__(128, 2)
void mma_gemm(const __half* __restrict__ A, const __half* __restrict__ B,
              void* __restrict__ Cv, const float* __restrict__ bias,
              const float* __restrict__ resid,
              int lda, int ldb, int ldc,
              long aB, long bB, long cB, float scale)
{
    extern __shared__ float sm[];
    const int TILEB = 128 * 128, STGB = 2 * TILEB;

    int t = threadIdx.x, lane = t & 31, w = t >> 5;
    int wr = w & 1, wc = w >> 1;
    int g = lane >> 2, tg = lane & 3;
    int lo7 = lane & 7;
    int hiA = lane >> 4, hiB = (lane >> 3) & 1;
    int bz = blockIdx.z, m0 = blockIdx.y * 128, n0 = blockIdx.x * 128;
    const __half* Ab = A + (size_t)bz * aB;
    const __half* Bb = B + (size_t)bz * bB;

    float acc[4][8][4];
    #pragma unroll
    for (int i = 0; i < 4; i++)
        #pragma unroll
        for (int j = 0; j < 8; j++)
            #pragma unroll
            for (int q = 0; q < 4; q++) acc[i][j][q] = 0.f;

    GEMM_MAINLOOP(Ab, Bb, lda, ldb, NC)

    int mrow = m0 + wr * 64, ncol = n0 + wc * 64;
    #pragma unroll
    for (int i = 0; i < 4; i++) {
        int r0 = mrow + i * 16 + g, r1 = r0 + 8;
        float bm0 = 0.f, bm1 = 0.f;
        if (EPI == 3) { bm0 = __ldg(&bias[r0]); bm1 = __ldg(&bias[r1]); }
        #pragma unroll
        for (int j = 0; j < 8; j++) {
            int cc = ncol + j * 8 + 2 * tg;
            float2 v0 = make_float2(acc[i][j][0], acc[i][j][1]);
            float2 v1 = make_float2(acc[i][j][2], acc[i][j][3]);
            if (EPI == 1) {
                __half* Cb = (__half*)Cv + (size_t)bz * cB;
                *(__half2*)(Cb + (size_t)r0 * ldc + cc) = __floats2half2_rn(v0.x * scale, v0.y * scale);
                *(__half2*)(Cb + (size_t)r1 * ldc + cc) = __floats2half2_rn(v1.x * scale, v1.y * scale);
            } else if (EPI == 2) {
                __half* Cb = (__half*)Cv + (size_t)bz * cB;
                *(__half2*)(Cb + (size_t)r0 * ldc + cc) = __floats2half2_rn(v0.x, v0.y);
                *(__half2*)(Cb + (size_t)r1 * ldc + cc) = __floats2half2_rn(v1.x, v1.y);
            } else {
                float* Cb = (float*)Cv + (size_t)bz * cB;
                const float* Rb = resid + (size_t)bz * cB;
                float2 x0 = *(const float2*)(Rb + (size_t)r0 * ldc + cc);
                float2 x1 = *(const float2*)(Rb + (size_t)r1 * ldc + cc);
                v0.x += bm0 + x0.x; v0.y += bm0 + x0.y;
                v1.x += bm1 + x1.x; v1.y += bm1 + x1.y;
                *(float2*)(Cb + (size_t)r0 * ldc + cc) = v0;
                *(float2*)(Cb + (size_t)r1 * ldc + cc) = v1;
            }
        }
    }
}

// ---------------------------------------------------------------------------
// GroupNorm (grid.y = 0,1) + weight fp32->fp16 conversion (grid.y = 2) in one
// launch. GN: one block per (b, group), fp16 transposed output [b][hw][c].
// cvt: 512 blocks x 256 threads x 8 elems = 1M elements (4 matrices, no
// matrix straddle: 2048 | 262144).
// ---------------------------------------------------------------------------
__global__ void gn_t_kernel(const float* __restrict__ x0, const float* __restrict__ sc0,
                            const float* __restrict__ bi0, __half* __restrict__ o0,
                            const float* __restrict__ x1, const float* __restrict__ sc1,
                            const float* __restrict__ bi1, __half* __restrict__ o1,
                            const float* __restrict__ wq, const float* __restrict__ wk,
                            const float* __restrict__ wv, const float* __restrict__ wp,
                            __half* __restrict__ wh)
{
    extern __shared__ float xs[];      // 16 * 1026
    __shared__ float shs[8], shq[8], shm2[2];

    if (blockIdx.y == 2) {
        size_t base = (size_t)blockIdx.x * 2048 + (size_t)threadIdx.x * 8;
        int mat = (int)(base >> 18);                // /262144
        size_t off = base & 0x3FFFF;
        const float* src = mat == 0 ? wq : (mat == 1 ? wk : (mat == 2 ? wv : wp));
        float4 v0 = *(const float4*)(src + off);
        float4 v1 = *(const float4*)(src + off + 4);
        __half2* d = (__half2*)(wh + base);
        d[0] = __floats2half2_rn(v0.x, v0.y);
        d[1] = __floats2half2_rn(v0.z, v0.w);
        d[2] = __floats2half2_rn(v1.x, v1.y);
        d[3] = __floats2half2_rn(v1.z, v1.w);
        return;
    }

    const float* x  = blockIdx.y ? x1  : x0;
    const float* sc = blockIdx.y ? sc1 : sc0;
    const float* bi = blockIdx.y ? bi1 : bi0;
    __half* outT    = blockIdx.y ? o1  : o0;
    int bg = blockIdx.x;
    int b = bg >> 5, g = bg & 31;
    const float* xp = x + ((size_t)b * CC + (size_t)g * 16) * HWW;
    int t = threadIdx.x;

    float s = 0.f, sq = 0.f;
    #pragma unroll 4
    for (int j = 0; j < 64; j++) {
        int idx = t + 256 * j;               // idx = c*1024 + hw
        float v = xp[idx];
        xs[(idx >> 10) * 1026 + (idx & 1023)] = v;
        s += v; sq += v * v;
    }
    #pragma unroll
    for (int o = 16; o > 0; o >>= 1) {
        s  += __shfl_xor_sync(0xffffffffu, s,  o);
        sq += __shfl_xor_sync(0xffffffffu, sq, o);
    }
    if ((t & 31) == 0) { shs[t >> 5] = s; shq[t >> 5] = sq; }
    __syncthreads();
    if (t == 0) {
        float S = 0.f, Q = 0.f;
        #pragma unroll
        for (int i = 0; i < 8; i++) { S += shs[i]; Q += shq[i]; }
        float mean = S * (1.f / 16384.f);
        float var  = Q * (1.f / 16384.f) - mean * mean;
        shm2[0] = mean;
        shm2[1] = rsqrtf(var + 1e-6f);
    }
    __syncthreads();
    float mean = shm2[0], rs = shm2[1];
    int cl = t & 15;
    float scv = __ldg(&sc[g * 16 + cl]) * rs;
    float biv = __ldg(&bi[g * 16 + cl]);
    __half* op = outT + (size_t)b * HWW * CC + g * 16;
    #pragma unroll 4
    for (int j = 0; j < 64; j++) {
        int idx = t + 256 * j;
        int hw = idx >> 4;
        op[(size_t)hw * CC + cl] = __float2half_rn((xs[cl * 1026 + hw] - mean) * scv + biv);
    }
}

// ---------------------------------------------------------------------------
// In-place fp16 row softmax: 2 rows per 256-thread block, uint4 loads.
// ---------------------------------------------------------------------------
__global__ void softmax_kernel(__half* __restrict__ Sh)
{
    __shared__ float red[2][4];
    int t = threadIdx.x;
    int r = t >> 7, tt = t & 127;
    int w4 = (t >> 5) & 3;
    size_t row = (size_t)blockIdx.x * 2 + r;
    uint4* p = (uint4*)(Sh + row * HWW);

    uint4 u = p[tt];
    __half2 h[4];
    h[0] = *(__half2*)&u.x; h[1] = *(__half2*)&u.y;
    h[2] = *(__half2*)&u.z; h[3] = *(__half2*)&u.w;
    float2 a[4];
    #pragma unroll
    for (int i = 0; i < 4; i++) a[i] = __half22float2(h[i]);

    float m = a[0].x;
    #pragma unroll
    for (int i = 0; i < 4; i++) m = fmaxf(m, fmaxf(a[i].x, a[i].y));
    #pragma unroll
    for (int o = 16; o > 0; o >>= 1) m = fmaxf(m, __shfl_xor_sync(0xffffffffu, m, o));
    if ((t & 31) == 0) red[r][w4] = m;
    __syncthreads();
    float M = fmaxf(fmaxf(red[r][0], red[r][1]), fmaxf(red[r][2], red[r][3]));
    __syncthreads();

    float s = 0.f;
    #pragma unroll
    for (int i = 0; i < 4; i++) {
        a[i].x = __expf(a[i].x - M); a[i].y = __expf(a[i].y - M);
        s += a[i].x + a[i].y;
    }
    #pragma unroll
    for (int o = 16; o > 0; o >>= 1) s += __shfl_xor_sync(0xffffffffu, s, o);
    if ((t & 31) == 0) red[r][w4] = s;
    __syncthreads();
    float T = red[r][0] + red[r][1] + red[r][2] + red[r][3];
    float inv = 1.0f / T;

    __half2 o2[4];
    #pragma unroll
    for (int i = 0; i < 4; i++) o2[i] = __floats2half2_rn(a[i].x * inv, a[i].y * inv);
    uint4 ou;
    ou.x = *(uint32_t*)&o2[0]; ou.y = *(uint32_t*)&o2[1];
    ou.z = *(uint32_t*)&o2[2]; ou.w = *(uint32_t*)&o2[3];
    p[tt] = ou;
}

// ---------------------------------------------------------------------------
extern "C" void kernel_launch(void* const* d_in, const int* in_sizes, int n_in,
                              void* d_out, int out_size)
{
    const float* x   = (const float*)d_in[0];
    const float* y   = (const float*)d_in[1];
    const float* ns  = (const float*)d_in[2];
    const float* nb  = (const float*)d_in[3];
    const float* n1s = (const float*)d_in[4];
    const float* n1b = (const float*)d_in[5];
    const float* wq  = (const float*)d_in[6];
    const float* bq  = (const float*)d_in[7];
    const float* wk  = (const float*)d_in[8];
    const float* bk  = (const float*)d_in[9];
    const float* wv  = (const float*)d_in[10];
    const float* bv  = (const float*)d_in[11];
    const float* wp  = (const float*)d_in[12];
    const float* bp  = (const float*)d_in[13];
    float* out = (float*)d_out;

    __half *hxT, *hyT, *qT, *kT, *v2, *wh, *sh;
    cudaGetSymbolAddress((void**)&hxT, g_hxT);
    cudaGetSymbolAddress((void**)&hyT, g_hyT);
    cudaGetSymbolAddress((void**)&qT,  g_qT);
    cudaGetSymbolAddress((void**)&kT,  g_kT);
    cudaGetSymbolAddress((void**)&v2,  g_v2);
    cudaGetSymbolAddress((void**)&wh,  g_wh);
    cudaGetSymbolAddress((void**)&sh,  g_sh);
    __half* O = hxT;   // hxT dead after qkv kernel
    __half* whp = wh + 3 * (size_t)CC * CC;

    const int SMEM_GEMM = 3 * 2 * 128 * 128;         // 98304 B
    const int SMEM_GN   = 16 * 1026 * sizeof(float); // 65664 B
    cudaFuncSetAttribute(mma_qkv,         cudaFuncAttributeMaxDynamicSharedMemorySize, SMEM_GEMM);
    cudaFuncSetAttribute(mma_gemm<1, 8>,  cudaFuncAttributeMaxDynamicSharedMemorySize, SMEM_GEMM);
    cudaFuncSetAttribute(mma_gemm<2, 16>, cudaFuncAttributeMaxDynamicSharedMemorySize, SMEM_GEMM);
    cudaFuncSetAttribute(mma_gemm<3, 8>,  cudaFuncAttributeMaxDynamicSharedMemorySize, SMEM_GEMM);
    cudaFuncSetAttribute(gn_t_kernel,     cudaFuncAttributeMaxDynamicSharedMemorySize, SMEM_GN);

    const long AS = (long)CC * HWW;
    const long SS = (long)HWW * HWW;
    const float qkscale = 0.044194173824159216f;   // 512^-0.5

    // GroupNorm x/y + weight conversion, single launch (grid.y: 0,1=GN, 2=cvt)
    gn_t_kernel<<<dim3(BB * 32, 3), 256, SMEM_GN>>>(x, ns, nb, hxT, y, n1s, n1b, hyT,
                                                    wq, wk, wv, wp, wh);

    // q, k, v in ONE launch: grid.z = batch + 16*which
    mma_qkv<<<dim3(CC / 128, HWW / 128, 3 * BB), 128, SMEM_GEMM>>>(
        hyT, hxT, wh, qT, kT, v2, bq, bk, bv);

    // scores: Sh[i,j] = half(scale * sum_c qT[i,c] * kT[j,c])
    dim3 gqk(HWW / 128, HWW / 128, BB);   // (8, 8, 16)
    mma_gemm<1, 8><<<gqk, 128, SMEM_GEMM>>>(qT, kT, sh, nullptr, nullptr,
                                            CC, CC, HWW, AS, AS, SS, qkscale);

    softmax_kernel<<<BB * HWW / 2, 256>>>(sh);

    // O[i, c] = sum_j probs[i,j] * v2[c,j]  (half out)
    dim3 gav(CC / 128, HWW / 128, BB);    // (4, 8, 16)
    mma_gemm<2, 16><<<gav, 128, SMEM_GEMM>>>(sh, v2, O, nullptr, nullptr,
                                             HWW, HWW, CC, SS, AS, AS, 0.f);

    // out[oc, hw] = sum_c wp[oc,c] * O[hw,c] + bp[oc] + x  (fp32 out)
    dim3 gproj(HWW / 128, CC / 128, BB);  // (8, 4, 16)
    mma_gemm<3, 8><<<gproj, 128, SMEM_GEMM>>>(whp, O, out, bp, x,
                                              CC, CC, HWW, 0, AS, AS, 0.f);
}

// round 17
// speedup vs baseline: 1.1611x; 1.0343x over previous
#include <cuda_runtime.h>
#include <cuda_fp16.h>
#include <cstdint>
#include <math.h>

#define BB   16
#define CC   512
#define HWW  1024
#define ABUF ((size_t)BB*CC*HWW)      // 8M elements

// Scratch (__device__ globals; no allocs allowed)
__device__ __half g_hxT[ABUF];   // normalized x, [b][hw][c] fp16; reused as O
__device__ __half g_hyT[ABUF];   // normalized y, [b][hw][c] fp16
__device__ __half g_qT [ABUF];   // [b][hw][c]
__device__ __half g_kT [ABUF];   // [b][hw][c]
__device__ __half g_v2 [ABUF];   // [b][c][hw]
__device__ __half g_wh [4*(size_t)CC*CC];       // fp16 weights: q,k,v,p
__device__ __half g_sh [(size_t)BB*HWW*HWW];    // fp16 scores -> probs (in-place)

__device__ __forceinline__ uint32_t smem_u32(const void* p) {
    uint32_t a;
    asm("{ .reg .u64 t; cvta.to.shared.u64 t, %1; cvt.u32.u64 %0, t; }" : "=r"(a) : "l"(p));
    return a;
}
#define CP_ASYNC16(sa, ga) \
    asm volatile("cp.async.cg.shared.global [%0], [%1], 16;" :: "r"(sa), "l"(ga) : "memory")
#define CP_COMMIT() asm volatile("cp.async.commit_group;" ::: "memory")
#define CP_WAIT1()  asm volatile("cp.async.wait_group 1;" ::: "memory")
#define CP_WAIT0()  asm volatile("cp.async.wait_group 0;" ::: "memory")

__device__ __forceinline__ void ldsm4(uint32_t& r0, uint32_t& r1, uint32_t& r2,
                                      uint32_t& r3, uint32_t addr) {
    asm volatile("ldmatrix.sync.aligned.m8n8.x4.shared.b16 {%0,%1,%2,%3}, [%4];"
                 : "=r"(r0), "=r"(r1), "=r"(r2), "=r"(r3) : "r"(addr));
}
#define HMMA16816(acc, a, b) \
    asm volatile( \
        "mma.sync.aligned.m16n8k16.row.col.f32.f16.f16.f32 " \
        "{%0,%1,%2,%3},{%4,%5,%6,%7},{%8,%9},{%0,%1,%2,%3};" \
        : "+f"(acc[0]), "+f"(acc[1]), "+f"(acc[2]), "+f"(acc[3]) \
        : "r"(a[0]), "r"(a[1]), "r"(a[2]), "r"(a[3]), "r"(b[0]), "r"(b[1]))

// 128x128 tile, 3-stage cp.async, K-chunk 64 halves, XOR swizzle, ldmatrix.x4,
// register-double-buffered k16 steps. NC must be a compile-time constant at
// the expansion site for full unroll.
#define GEMM_MAINLOOP(Ab, Bb, lda, ldb, NC)                                          \
    uint32_t smb = smem_u32(sm);                                                      \
    uint32_t rowA_off = (uint32_t)((wr * 64 + (lane & 15)) * 128);                    \
    uint32_t rowB_off = (uint32_t)((wc * 64 + lo7 + ((lane & 16) >> 1)) * 128);       \
    auto load = [&](int c, int s) {                                                   \
        int k0 = c * 64;                                                              \
        _Pragma("unroll")                                                             \
        for (int j = 0; j < 8; j++) {                                                 \
            int idx2 = t + 128 * j;                                                   \
            int r = idx2 >> 3, cq = idx2 & 7;                                         \
            int cs = cq ^ (r & 7);                                                    \
            const __half* ga = Ab + (size_t)(m0 + r) * lda + k0 + cq * 8;             \
            const __half* gb = Bb + (size_t)(n0 + r) * ldb + k0 + cq * 8;             \
            uint32_t so = (uint32_t)(s * STGB + r * 128 + cs * 16);                   \
            CP_ASYNC16(smb + so, ga);                                                 \
            CP_ASYNC16(smb + (uint32_t)TILEB + so, gb);                               \
        }                                                                             \
    };                                                                                \
    auto ldfrag = [&](uint32_t aBase, uint32_t bBase, int s16,                        \
                      uint32_t (&af)[4][4], uint32_t (&bf)[8][2]) {                   \
        uint32_t slA = (uint32_t)(((2 * s16 + hiA) ^ lo7) << 4);                      \
        uint32_t slB = (uint32_t)(((2 * s16 + hiB) ^ lo7) << 4);                      \
        uint32_t aAddr = aBase + rowA_off + slA;                                      \
        uint32_t bAddr = bBase + rowB_off + slB;                                      \
        _Pragma("unroll")                                                             \
        for (int i = 0; i < 4; i++)                                                   \
            ldsm4(af[i][0], af[i][1], af[i][2], af[i][3],                             \
                  aAddr + (uint32_t)(i * 16 * 128));                                  \
        _Pragma("unroll")                                                             \
        for (int p = 0; p < 4; p++)                                                   \
            ldsm4(bf[2 * p][0], bf[2 * p][1], bf[2 * p + 1][0], bf[2 * p + 1][1],     \
                  bAddr + (uint32_t)(p * 16 * 128));                                  \
    };                                                                                \
    load(0, 0); CP_COMMIT();                                                          \
    if (NC > 1) { load(1, 1); CP_COMMIT(); }                                          \
    uint32_t af[2][4][4], bf[2][8][2];                                                \
    _Pragma("unroll")                                                                 \
    for (int c = 0; c < NC; c++) {                                                    \
        if (c + 1 < NC) CP_WAIT1(); else CP_WAIT0();                                  \
        __syncthreads();                                                              \
        uint32_t aBase = smb + (uint32_t)((c % 3) * STGB);                            \
        uint32_t bBase = aBase + (uint32_t)TILEB;                                     \
        ldfrag(aBase, bBase, 0, af[0], bf[0]);                                        \
        if (c + 2 < NC) { load(c + 2, (c + 2) % 3); CP_COMMIT(); }                    \
        _Pragma("unroll")                                                             \
        for (int s16 = 0; s16 < 4; s16++) {                                           \
            if (s16 < 3) ldfrag(aBase, bBase, s16 + 1, af[(s16 + 1) & 1], bf[(s16 + 1) & 1]); \
            uint32_t (&a)[4][4] = af[s16 & 1];                                        \
            uint32_t (&b)[8][2] = bf[s16 & 1];                                        \
            _Pragma("unroll")                                                         \
            for (int i = 0; i < 4; i++)                                               \
                _Pragma("unroll")                                                     \
                for (int j = 0; j < 8; j++)                                           \
                    HMMA16816(acc[i][j], a[i], b[j]);                                 \
        }                                                                             \
    }

// ---------------------------------------------------------------------------
// Merged q/k/v kernel: grid (4, 8, 48); z = batch + 16*which (0=q,1=k,2=v).
// q/k: +bias[n] half store [hw][c]. v: +bias[n] transposed half store [c][hw].
// ---------------------------------------------------------------------------
__global__ __launch_bounds__(128, 2)
void mma_qkv(const __half* __restrict__ hyT, const __half* __restrict__ hxT,
             const __half* __restrict__ wh,
             __half* __restrict__ qT, __half* __restrict__ kT, __half* __restrict__ v2,
             const float* __restrict__ bq, const float* __restrict__ bk,
             const float* __restrict__ bv)
{
    extern __shared__ float sm[];
    const int TILEB = 128 * 128, STGB = 2 * TILEB;
    const long AS = (long)CC * HWW;

    int t = threadIdx.x, lane = t & 31, w = t >> 5;
    int wr = w & 1, wc = w >> 1;
    int g = lane >> 2, tg = lane & 3;
    int lo7 = lane & 7;
    int hiA = lane >> 4, hiB = (lane >> 3) & 1;
    int z = blockIdx.z;
    int bz = z & 15, which = z >> 4;
    int m0 = blockIdx.y * 128, n0 = blockIdx.x * 128;

    const __half* Ab = (which == 0 ? hyT : hxT) + (size_t)bz * AS;
    const __half* Bb = wh + (size_t)which * CC * CC;
    const float* bias = which == 0 ? bq : (which == 1 ? bk : bv);

    float acc[4][8][4];
    #pragma unroll
    for (int i = 0; i < 4; i++)
        #pragma unroll
        for (int j = 0; j < 8; j++)
            #pragma unroll
            for (int q = 0; q < 4; q++) acc[i][j][q] = 0.f;

    GEMM_MAINLOOP(Ab, Bb, CC, CC, 8)

    if (which < 2) {
        __half* Cb = (which ? kT : qT) + (size_t)bz * AS;
        int mrow = m0 + wr * 64, ncol = n0 + wc * 64;
        #pragma unroll
        for (int i = 0; i < 4; i++) {
            int r0 = mrow + i * 16 + g, r1 = r0 + 8;
            #pragma unroll
            for (int j = 0; j < 8; j++) {
                int cc = ncol + j * 8 + 2 * tg;
                float b0 = __ldg(&bias[cc]), b1 = __ldg(&bias[cc + 1]);
                *(__half2*)(Cb + (size_t)r0 * CC + cc) =
                    __floats2half2_rn(acc[i][j][0] + b0, acc[i][j][1] + b1);
                *(__half2*)(Cb + (size_t)r1 * CC + cc) =
                    __floats2half2_rn(acc[i][j][2] + b0, acc[i][j][3] + b1);
            }
        }
    } else {
        // transposed store via fp32 smem staging (pad 129)
        __half* Cb = v2 + (size_t)bz * AS;
        __syncthreads();
        #pragma unroll
        for (int i = 0; i < 4; i++) {
            int rl0 = wr * 64 + i * 16 + g, rl1 = rl0 + 8;
            #pragma unroll
            for (int j = 0; j < 8; j++) {
                int nl = wc * 64 + j * 8 + 2 * tg;
                float b0 = __ldg(&bias[n0 + nl]), b1 = __ldg(&bias[n0 + nl + 1]);
                sm[(nl + 0) * 129 + rl0] = acc[i][j][0] + b0;
                sm[(nl + 1) * 129 + rl0] = acc[i][j][1] + b1;
                sm[(nl + 0) * 129 + rl1] = acc[i][j][2] + b0;
                sm[(nl + 1) * 129 + rl1] = acc[i][j][3] + b1;
            }
        }
        __syncthreads();
        #pragma unroll 4
        for (int rr = 0; rr < 32; rr++) {
            int rloc = w * 32 + rr;
            __half* dst = Cb + (size_t)(n0 + rloc) * HWW + m0;
            const float* srcr = sm + rloc * 129;
            #pragma unroll
            for (int k2 = 0; k2 < 4; k2++)
                dst[lane + 32 * k2] = __float2half_rn(srcr[lane + 32 * k2]);
        }
    }
}

// ---------------------------------------------------------------------------
// Generic fp16 GEMM, NC compile-time.
// EPI: 1=*scale->half | 2=none->half | 3=+bias[m]+resid->f32
// ---------------------------------------------------------------------------
template<int EPI, int NC>
__global__ __launch_bounds__(128, 2)
void mma_gemm(const __half* __restrict__ A, const __half* __restrict__ B,
              void* __restrict__ Cv, const float* __restrict__ bias,
              const float* __restrict__ resid,
              int lda, int ldb, int ldc,
              long aB, long bB, long cB, float scale)
{
    extern __shared__ float sm[];
    const int TILEB = 128 * 128, STGB = 2 * TILEB;

    int t = threadIdx.x, lane = t & 31, w = t >> 5;
    int wr = w & 1, wc = w >> 1;
    int g = lane >> 2, tg = lane & 3;
    int lo7 = lane & 7;
    int hiA = lane >> 4, hiB = (lane >> 3) & 1;
    int bz = blockIdx.z, m0 = blockIdx.y * 128, n0 = blockIdx.x * 128;
    const __half* Ab = A + (size_t)bz * aB;
    const __half* Bb = B + (size_t)bz * bB;

    float acc[4][8][4];
    #pragma unroll
    for (int i = 0; i < 4; i++)
        #pragma unroll
        for (int j = 0; j < 8; j++)
            #pragma unroll
            for (int q = 0; q < 4; q++) acc[i][j][q] = 0.f;

    GEMM_MAINLOOP(Ab, Bb, lda, ldb, NC)

    int mrow = m0 + wr * 64, ncol = n0 + wc * 64;
    #pragma unroll
    for (int i = 0; i < 4; i++) {
        int r0 = mrow + i * 16 + g, r1 = r0 + 8;
        float bm0 = 0.f, bm1 = 0.f;
        if (EPI == 3) { bm0 = __ldg(&bias[r0]); bm1 = __ldg(&bias[r1]); }
        #pragma unroll
        for (int j = 0; j < 8; j++) {
            int cc = ncol + j * 8 + 2 * tg;
            float2 v0 = make_float2(acc[i][j][0], acc[i][j][1]);
            float2 v1 = make_float2(acc[i][j][2], acc[i][j][3]);
            if (EPI == 1) {
                __half* Cb = (__half*)Cv + (size_t)bz * cB;
                *(__half2*)(Cb + (size_t)r0 * ldc + cc) = __floats2half2_rn(v0.x * scale, v0.y * scale);
                *(__half2*)(Cb + (size_t)r1 * ldc + cc) = __floats2half2_rn(v1.x * scale, v1.y * scale);
            } else if (EPI == 2) {
                __half* Cb = (__half*)Cv + (size_t)bz * cB;
                *(__half2*)(Cb + (size_t)r0 * ldc + cc) = __floats2half2_rn(v0.x, v0.y);
                *(__half2*)(Cb + (size_t)r1 * ldc + cc) = __floats2half2_rn(v1.x, v1.y);
            } else {
                float* Cb = (float*)Cv + (size_t)bz * cB;
                const float* Rb = resid + (size_t)bz * cB;
                float2 x0 = *(const float2*)(Rb + (size_t)r0 * ldc + cc);
                float2 x1 = *(const float2*)(Rb + (size_t)r1 * ldc + cc);
                v0.x += bm0 + x0.x; v0.y += bm0 + x0.y;
                v1.x += bm1 + x1.x; v1.y += bm1 + x1.y;
                *(float2*)(Cb + (size_t)r0 * ldc + cc) = v0;
                *(float2*)(Cb + (size_t)r1 * ldc + cc) = v1;
            }
        }
    }
}

// ---------------------------------------------------------------------------
// GroupNorm (grid.y = 0,1) + weight fp32->fp16 conversion (grid.y = 2) in one
// launch. GN: one block per (b, group), fp16 transposed output [b][hw][c].
// Stats pass uses float4 loads (pad 1028 keeps smem stores 16B-aligned).
// cvt: 512 blocks x 256 threads x 8 elems = 1M elements.
// ---------------------------------------------------------------------------
__global__ void gn_t_kernel(const float* __restrict__ x0, const float* __restrict__ sc0,
                            const float* __restrict__ bi0, __half* __restrict__ o0,
                            const float* __restrict__ x1, const float* __restrict__ sc1,
                            const float* __restrict__ bi1, __half* __restrict__ o1,
                            const float* __restrict__ wq, const float* __restrict__ wk,
                            const float* __restrict__ wv, const float* __restrict__ wp,
                            __half* __restrict__ wh)
{
    extern __shared__ float xs[];      // 16 * 1028
    __shared__ float shs[8], shq[8], shm2[2];

    if (blockIdx.y == 2) {
        size_t base = (size_t)blockIdx.x * 2048 + (size_t)threadIdx.x * 8;
        int mat = (int)(base >> 18);                // /262144
        size_t off = base & 0x3FFFF;
        const float* src = mat == 0 ? wq : (mat == 1 ? wk : (mat == 2 ? wv : wp));
        float4 v0 = *(const float4*)(src + off);
        float4 v1 = *(const float4*)(src + off + 4);
        __half2* d = (__half2*)(wh + base);
        d[0] = __floats2half2_rn(v0.x, v0.y);
        d[1] = __floats2half2_rn(v0.z, v0.w);
        d[2] = __floats2half2_rn(v1.x, v1.y);
        d[3] = __floats2half2_rn(v1.z, v1.w);
        return;
    }

    const float* x  = blockIdx.y ? x1  : x0;
    const float* sc = blockIdx.y ? sc1 : sc0;
    const float* bi = blockIdx.y ? bi1 : bi0;
    __half* outT    = blockIdx.y ? o1  : o0;
    int bg = blockIdx.x;
    int b = bg >> 5, g = bg & 31;
    const float* xp = x + ((size_t)b * CC + (size_t)g * 16) * HWW;
    int t = threadIdx.x;

    // Stats + smem fill via float4: thread t, iter j covers c=j, hw=4t..4t+3
    float s = 0.f, sq = 0.f;
    #pragma unroll 4
    for (int j = 0; j < 16; j++) {
        float4 v = *(const float4*)(xp + (size_t)j * HWW + 4 * t);
        *(float4*)(xs + j * 1028 + 4 * t) = v;
        s += v.x + v.y + v.z + v.w;
        sq += v.x * v.x + v.y * v.y + v.z * v.z + v.w * v.w;
    }
    #pragma unroll
    for (int o = 16; o > 0; o >>= 1) {
        s  += __shfl_xor_sync(0xffffffffu, s,  o);
        sq += __shfl_xor_sync(0xffffffffu, sq, o);
    }
    if ((t & 31) == 0) { shs[t >> 5] = s; shq[t >> 5] = sq; }
    __syncthreads();
    if (t == 0) {
        float S = 0.f, Q = 0.f;
        #pragma unroll
        for (int i = 0; i < 8; i++) { S += shs[i]; Q += shq[i]; }
        float mean = S * (1.f / 16384.f);
        float var  = Q * (1.f / 16384.f) - mean * mean;
        shm2[0] = mean;
        shm2[1] = rsqrtf(var + 1e-6f);
    }
    __syncthreads();
    float mean = shm2[0], rs = shm2[1];
    int cl = t & 15;
    float scv = __ldg(&sc[g * 16 + cl]) * rs;
    float biv = __ldg(&bi[g * 16 + cl]);
    __half* op = outT + (size_t)b * HWW * CC + g * 16;
    #pragma unroll 4
    for (int j = 0; j < 64; j++) {
        int idx = t + 256 * j;
        int hw = idx >> 4;
        op[(size_t)hw * CC + cl] = __float2half_rn((xs[cl * 1028 + hw] - mean) * scv + biv);
    }
}

// ---------------------------------------------------------------------------
// In-place fp16 row softmax, half2 math end-to-end (reductions in fp32).
// 2 rows per 256-thread block, uint4 (8-half) loads.
// ---------------------------------------------------------------------------
__global__ void softmax_kernel(__half* __restrict__ Sh)
{
    __shared__ float red[2][4];
    int t = threadIdx.x;
    int r = t >> 7, tt = t & 127;
    int w4 = (t >> 5) & 3;
    size_t row = (size_t)blockIdx.x * 2 + r;
    uint4* p = (uint4*)(Sh + row * HWW);

    uint4 u = p[tt];
    __half2 h[4];
    h[0] = *(__half2*)&u.x; h[1] = *(__half2*)&u.y;
    h[2] = *(__half2*)&u.z; h[3] = *(__half2*)&u.w;

    // max in half2, finish in fp32 for the shuffle reduction
    __half2 m2 = __hmax2(__hmax2(h[0], h[1]), __hmax2(h[2], h[3]));
    float m = fmaxf(__low2float(m2), __high2float(m2));
    #pragma unroll
    for (int o = 16; o > 0; o >>= 1) m = fmaxf(m, __shfl_xor_sync(0xffffffffu, m, o));
    if ((t & 31) == 0) red[r][w4] = m;
    __syncthreads();
    float M = fmaxf(fmaxf(red[r][0], red[r][1]), fmaxf(red[r][2], red[r][3]));
    __syncthreads();

    // exp in half2 (h2exp = HMUL2+EX2.F16x2), partial sums in half2 then fp32
    __half2 M2 = __float2half2_rn(M);
    __half2 e[4];
    #pragma unroll
    for (int i = 0; i < 4; i++) e[i] = h2exp(__hsub2(h[i], M2));
    __half2 s2 = __hadd2(__hadd2(e[0], e[1]), __hadd2(e[2], e[3]));
    float s = __low2float(s2) + __high2float(s2);
    #pragma unroll
    for (int o = 16; o > 0; o >>= 1) s += __shfl_xor_sync(0xffffffffu, s, o);
    if ((t & 31) == 0) red[r][w4] = s;
    __syncthreads();
    float T = red[r][0] + red[r][1] + red[r][2] + red[r][3];
    __half2 inv2 = __float2half2_rn(1.0f / T);

    uint4 ou;
    __half2 o0 = __hmul2(e[0], inv2), o1 = __hmul2(e[1], inv2);
    __half2 o2 = __hmul2(e[2], inv2), o3 = __hmul2(e[3], inv2);
    ou.x = *(uint32_t*)&o0; ou.y = *(uint32_t*)&o1;
    ou.z = *(uint32_t*)&o2; ou.w = *(uint32_t*)&o3;
    p[tt] = ou;
}

// ---------------------------------------------------------------------------
extern "C" void kernel_launch(void* const* d_in, const int* in_sizes, int n_in,
                              void* d_out, int out_size)
{
    const float* x   = (const float*)d_in[0];
    const float* y   = (const float*)d_in[1];
    const float* ns  = (const float*)d_in[2];
    const float* nb  = (const float*)d_in[3];
    const float* n1s = (const float*)d_in[4];
    const float* n1b = (const float*)d_in[5];
    const float* wq  = (const float*)d_in[6];
    const float* bq  = (const float*)d_in[7];
    const float* wk  = (const float*)d_in[8];
    const float* bk  = (const float*)d_in[9];
    const float* wv  = (const float*)d_in[10];
    const float* bv  = (const float*)d_in[11];
    const float* wp  = (const float*)d_in[12];
    const float* bp  = (const float*)d_in[13];
    float* out = (float*)d_out;

    __half *hxT, *hyT, *qT, *kT, *v2, *wh, *sh;
    cudaGetSymbolAddress((void**)&hxT, g_hxT);
    cudaGetSymbolAddress((void**)&hyT, g_hyT);
    cudaGetSymbolAddress((void**)&qT,  g_qT);
    cudaGetSymbolAddress((void**)&kT,  g_kT);
    cudaGetSymbolAddress((void**)&v2,  g_v2);
    cudaGetSymbolAddress((void**)&wh,  g_wh);
    cudaGetSymbolAddress((void**)&sh,  g_sh);
    __half* O = hxT;   // hxT dead after qkv kernel
    __half* whp = wh + 3 * (size_t)CC * CC;

    const int SMEM_GEMM = 3 * 2 * 128 * 128;         // 98304 B
    const int SMEM_GN   = 16 * 1028 * sizeof(float); // 65792 B
    cudaFuncSetAttribute(mma_qkv,         cudaFuncAttributeMaxDynamicSharedMemorySize, SMEM_GEMM);
    cudaFuncSetAttribute(mma_gemm<1, 8>,  cudaFuncAttributeMaxDynamicSharedMemorySize, SMEM_GEMM);
    cudaFuncSetAttribute(mma_gemm<2, 16>, cudaFuncAttributeMaxDynamicSharedMemorySize, SMEM_GEMM);
    cudaFuncSetAttribute(mma_gemm<3, 8>,  cudaFuncAttributeMaxDynamicSharedMemorySize, SMEM_GEMM);
    cudaFuncSetAttribute(gn_t_kernel,     cudaFuncAttributeMaxDynamicSharedMemorySize, SMEM_GN);

    const long AS = (long)CC * HWW;
    const long SS = (long)HWW * HWW;
    const float qkscale = 0.044194173824159216f;   // 512^-0.5

    // GroupNorm x/y + weight conversion, single launch (grid.y: 0,1=GN, 2=cvt)
    gn_t_kernel<<<dim3(BB * 32, 3), 256, SMEM_GN>>>(x, ns, nb, hxT, y, n1s, n1b, hyT,
                                                    wq, wk, wv, wp, wh);

    // q, k, v in ONE launch: grid.z = batch + 16*which
    mma_qkv<<<dim3(CC / 128, HWW / 128, 3 * BB), 128, SMEM_GEMM>>>(
        hyT, hxT, wh, qT, kT, v2, bq, bk, bv);

    // scores: Sh[i,j] = half(scale * sum_c qT[i,c] * kT[j,c])
    dim3 gqk(HWW / 128, HWW / 128, BB);   // (8, 8, 16)
    mma_gemm<1, 8><<<gqk, 128, SMEM_GEMM>>>(qT, kT, sh, nullptr, nullptr,
                                            CC, CC, HWW, AS, AS, SS, qkscale);

    softmax_kernel<<<BB * HWW / 2, 256>>>(sh);

    // O[i, c] = sum_j probs[i,j] * v2[c,j]  (half out)
    dim3 gav(CC / 128, HWW / 128, BB);    // (4, 8, 16)
    mma_gemm<2, 16><<<gav, 128, SMEM_GEMM>>>(sh, v2, O, nullptr, nullptr,
                                             HWW, HWW, CC, SS, AS, AS, 0.f);

    // out[oc, hw] = sum_c wp[oc,c] * O[hw,c] + bp[oc] + x  (fp32 out)
    dim3 gproj(HWW / 128, CC / 128, BB);  // (8, 4, 16)
    mma_gemm<3, 8><<<gproj, 128, SMEM_GEMM>>>(whp, O, out, bp, x,
                                              CC, CC, HWW, 0, AS, AS, 0.f);
}